// round 9
// baseline (speedup 1.0000x reference)
#include <cuda_runtime.h>
#include <cuda_bf16.h>
#include <stdint.h>
#include <math.h>

#define B_ 8
#define S_ 2048
#define DSTATE 1024
#define H_ 16
#define DH_ 64
#define PROJW 4096
#define M_ (B_ * S_)          // 16384
#define KIN 1024
#define K3 (3 * KIN)          // 3072

// ---------------------------------------------------------------------------
// Scratch
// ---------------------------------------------------------------------------
__device__ float g_proj[(size_t)M_ * PROJW];              // 256 MB (fp32 truth)
__device__ float g_projtest[(size_t)M_ * PROJW];          // 256 MB (HMMA under test)
__device__ float g_hseq[(size_t)M_ * DSTATE];             // 64 MB
__device__ float g_y[(size_t)M_ * DSTATE];                // 64 MB
__device__ __nv_bfloat16 g_x3[(size_t)M_ * K3];           // 96 MB
__device__ __nv_bfloat16 g_wi3[(size_t)PROJW * K3];       // 24 MB

__device__ __forceinline__ float* sel_buf(int s, const void* ext) {
    switch (s) {
        case 1: return g_proj;
        case 2: return g_hseq;
        case 3: return g_y;
        default: return (float*)ext;
    }
}

#define MMA16816(d, a, b) \
    asm volatile("mma.sync.aligned.m16n8k16.row.col.f32.bf16.bf16.f32 " \
                 "{%0,%1,%2,%3},{%4,%5,%6,%7},{%8,%9},{%0,%1,%2,%3};" \
                 : "+f"((d)[0]), "+f"((d)[1]), "+f"((d)[2]), "+f"((d)[3]) \
                 : "r"((a)[0]), "r"((a)[1]), "r"((a)[2]), "r"((a)[3]), \
                   "r"((b)[0]), "r"((b)[1]))

__device__ __forceinline__ void split2(float v, __nv_bfloat16& h, __nv_bfloat16& l) {
    h = __float2bfloat16(v);
    l = __float2bfloat16(v - __bfloat162float(h));
}

// ---------------------------------------------------------------------------
// Suspect A: converts
// ---------------------------------------------------------------------------
__global__ __launch_bounds__(256) void convert_x3_kernel(const float* __restrict__ x)
{
    int row = blockIdx.x;
    int c = threadIdx.x;
    const float* xr = x + (size_t)row * KIN;
    __nv_bfloat16* o = g_x3 + (size_t)row * K3;
#pragma unroll
    for (int i = 0; i < 4; i++) {
        int k = c + i * 256;
        __nv_bfloat16 h, l;
        split2(xr[k], h, l);
        o[k] = h; o[KIN + k] = h; o[2 * KIN + k] = l;
    }
}

__global__ __launch_bounds__(256) void transpose_conv3_kernel(const float* __restrict__ in,
                                                              __nv_bfloat16* __restrict__ out,
                                                              int R, int C)
{
    __shared__ float t[32][33];
    const int tx = threadIdx.x, ty = threadIdx.y;
    const int c0 = blockIdx.x * 32, r0 = blockIdx.y * 32;
#pragma unroll
    for (int i = 0; i < 4; i++)
        t[ty + i * 8][tx] = in[(size_t)(r0 + ty + i * 8) * C + c0 + tx];
    __syncthreads();
#pragma unroll
    for (int i = 0; i < 4; i++) {
        float v = t[tx][ty + i * 8];
        __nv_bfloat16 h, l;
        split2(v, h, l);
        __nv_bfloat16* o = out + (size_t)(c0 + ty + i * 8) * (3 * R) + r0 + tx;
        o[0] = h; o[R] = l; o[2 * R] = h;
    }
}

// ---------------------------------------------------------------------------
// Suspect B: HMMA GEMM (R8 version) -> g_projtest (dead scratch)
// ---------------------------------------------------------------------------
#define ROWB 80
#define TILEB (128 * ROWB)

__global__ __launch_bounds__(256) void hmma_gemm1()
{
    __shared__ char smem[2 * TILEB];

    const __nv_bfloat16* Ap = g_x3;
    const __nv_bfloat16* Bp = g_wi3;
    float* C = g_projtest;
    const int Kt = K3, N = PROJW;

    const int tid = threadIdx.x;
    const int lane = tid & 31, wid = tid >> 5;
    const int warp_m = wid >> 2, warp_n = wid & 3;
    const int bm = blockIdx.y * 128, bn = blockIdx.x * 128;

    char* Asm = smem;
    char* Bsm = smem + TILEB;

    float acc[4][4][4] = {};
    const int nch = Kt >> 5;

    const int prow = tid >> 2;
    const int pkc  = tid & 3;

    uint4 pa0 = *(const uint4*)(Ap + (size_t)(bm + prow)      * Kt + pkc * 8);
    uint4 pa1 = *(const uint4*)(Ap + (size_t)(bm + prow + 64) * Kt + pkc * 8);
    uint4 pb0 = *(const uint4*)(Bp + (size_t)(bn + prow)      * Kt + pkc * 8);
    uint4 pb1 = *(const uint4*)(Bp + (size_t)(bn + prow + 64) * Kt + pkc * 8);

    const int g  = lane >> 2;
    const int t4 = lane & 3;

    for (int c = 0; c < nch; c++) {
        *(uint4*)(Asm + prow * ROWB + pkc * 16)        = pa0;
        *(uint4*)(Asm + (prow + 64) * ROWB + pkc * 16) = pa1;
        *(uint4*)(Bsm + prow * ROWB + pkc * 16)        = pb0;
        *(uint4*)(Bsm + (prow + 64) * ROWB + pkc * 16) = pb1;
        __syncthreads();

        if (c + 1 < nch) {
            const int cn = c + 1;
            pa0 = *(const uint4*)(Ap + (size_t)(bm + prow)      * Kt + cn * 32 + pkc * 8);
            pa1 = *(const uint4*)(Ap + (size_t)(bm + prow + 64) * Kt + cn * 32 + pkc * 8);
            pb0 = *(const uint4*)(Bp + (size_t)(bn + prow)      * Kt + cn * 32 + pkc * 8);
            pb1 = *(const uint4*)(Bp + (size_t)(bn + prow + 64) * Kt + cn * 32 + pkc * 8);
        }

#pragma unroll
        for (int ks = 0; ks < 2; ks++) {
            uint32_t a[4][4], b[4][2];
#pragma unroll
            for (int mt = 0; mt < 4; mt++) {
                const char* ab = Asm + (warp_m * 64 + mt * 16 + g) * ROWB + ks * 32 + t4 * 4;
                a[mt][0] = *(const uint32_t*)ab;
                a[mt][1] = *(const uint32_t*)(ab + 8 * ROWB);
                a[mt][2] = *(const uint32_t*)(ab + 16);
                a[mt][3] = *(const uint32_t*)(ab + 8 * ROWB + 16);
            }
#pragma unroll
            for (int nt = 0; nt < 4; nt++) {
                const char* bb = Bsm + (warp_n * 32 + nt * 8 + g) * ROWB + ks * 32 + t4 * 4;
                b[nt][0] = *(const uint32_t*)bb;
                b[nt][1] = *(const uint32_t*)(bb + 16);
            }
#pragma unroll
            for (int mt = 0; mt < 4; mt++)
#pragma unroll
                for (int nt = 0; nt < 4; nt++)
                    MMA16816(acc[mt][nt], a[mt], b[nt]);
        }
        __syncthreads();
    }

    const int r0 = bm + warp_m * 64 + g;
    const int c0 = bn + warp_n * 32 + t4 * 2;
#pragma unroll
    for (int mt = 0; mt < 4; mt++)
#pragma unroll
        for (int nt = 0; nt < 4; nt++) {
            *(float2*)&C[(size_t)(r0 + mt * 16) * N + c0 + nt * 8] =
                make_float2(acc[mt][nt][0], acc[mt][nt][1]);
            *(float2*)&C[(size_t)(r0 + mt * 16 + 8) * N + c0 + nt * 8] =
                make_float2(acc[mt][nt][2], acc[mt][nt][3]);
        }
}

// ---------------------------------------------------------------------------
// Timing-channel verdict kernels (deterministic; write nothing)
// ---------------------------------------------------------------------------
#define SPIN1 3000000LL   // converts bad  -> +~1.7 ms
#define SPIN2 6000000LL   // hmma mismatch -> +~3.4 ms

__global__ __launch_bounds__(256) void check_x3(const float* __restrict__ x)
{
    const size_t n = (size_t)M_ * KIN;
    const size_t stride = (size_t)gridDim.x * 256 * 16;   // sample 1/16
    bool bad = false;
    for (size_t i = (size_t)blockIdx.x * 256 + threadIdx.x; i < n; i += stride) {
        size_t row = i / KIN, k = i - row * KIN;
        float hi = __bfloat162float(g_x3[row * K3 + k]);
        float lo = __bfloat162float(g_x3[row * K3 + 2 * KIN + k]);
        if (fabsf(hi + lo - x[i]) > 1e-2f * (1.f + fabsf(x[i]))) bad = true;
    }
    if (__syncthreads_or(bad)) {
        long long t0 = clock64();
        while (clock64() - t0 < SPIN1) {}
    }
}

__global__ __launch_bounds__(256) void check_proj()
{
    const size_t n = (size_t)M_ * PROJW;
    const size_t stride = (size_t)gridDim.x * 256 * 64;   // sample 1/64
    bool bad = false;
    for (size_t i = (size_t)blockIdx.x * 256 + threadIdx.x; i < n; i += stride) {
        float ref = g_proj[i];
        float tst = g_projtest[i];
        if (fabsf(tst - ref) > 1e-2f * (1.f + fabsf(ref))) bad = true;
    }
    if (__syncthreads_or(bad)) {
        long long t0 = clock64();
        while (clock64() - t0 < SPIN2) {}
    }
}

// ---------------------------------------------------------------------------
// PROVEN fp32 GEMM (R3)
// ---------------------------------------------------------------------------
__global__ __launch_bounds__(256) void gemm128(const void* Aext, int a_sel,
                                               const float* __restrict__ Bm,
                                               void* Cext, int c_sel,
                                               int M, int N, int K)
{
    const float* __restrict__ A = sel_buf(a_sel, Aext);
    float* __restrict__ C = sel_buf(c_sel, Cext);

    __shared__ float As[8][128];
    __shared__ float Bs[8][128];

    const int tid = threadIdx.x;
    const int bm = blockIdx.y * 128;
    const int bn = blockIdx.x * 128;
    const int tx = tid & 15;
    const int ty = tid >> 4;

    float acc[8][8] = {};

    const int am = tid >> 1;
    const int ak = (tid & 1) * 4;
    const int bk  = tid >> 5;
    const int bn4 = (tid & 31) * 4;

    const float* Aptr = A + (size_t)(bm + am) * K + ak;
    const float* Bptr = Bm + (size_t)bk * N + bn + bn4;

    for (int k0 = 0; k0 < K; k0 += 8) {
        float4 av = *(const float4*)(Aptr + k0);
        float4 bv = *(const float4*)(Bptr + (size_t)k0 * N);
        As[ak + 0][am] = av.x;
        As[ak + 1][am] = av.y;
        As[ak + 2][am] = av.z;
        As[ak + 3][am] = av.w;
        *(float4*)&Bs[bk][bn4] = bv;
        __syncthreads();

#pragma unroll
        for (int k = 0; k < 8; k++) {
            float a[8], b[8];
            *(float4*)&a[0] = *(const float4*)&As[k][ty * 8];
            *(float4*)&a[4] = *(const float4*)&As[k][ty * 8 + 4];
            *(float4*)&b[0] = *(const float4*)&Bs[k][tx * 8];
            *(float4*)&b[4] = *(const float4*)&Bs[k][tx * 8 + 4];
#pragma unroll
            for (int i = 0; i < 8; i++)
#pragma unroll
                for (int j = 0; j < 8; j++)
                    acc[i][j] = fmaf(a[i], b[j], acc[i][j]);
        }
        __syncthreads();
    }

#pragma unroll
    for (int i = 0; i < 8; i++) {
        float* Crow = C + (size_t)(bm + ty * 8 + i) * N + bn + tx * 8;
        *(float4*)Crow       = make_float4(acc[i][0], acc[i][1], acc[i][2], acc[i][3]);
        *(float4*)(Crow + 4) = make_float4(acc[i][4], acc[i][5], acc[i][6], acc[i][7]);
    }
}

// ---------------------------------------------------------------------------
// Recurrence (proven)
// ---------------------------------------------------------------------------
__global__ __launch_bounds__(64, 1) void recur_kernel(const float* __restrict__ Wall)
{
    __shared__ float hs[64];
    __shared__ float rh[64];

    const int b = blockIdx.x >> 4;
    const int h = blockIdx.x & 15;
    const int e = threadIdx.x;

    float wc[64], wf[64], wr[64];
    const float* Wc = Wall + (size_t)h * 4096 + e;
    const float* Wf = Wall + (size_t)(16 + h) * 4096 + e;
    const float* Wr = Wall + (size_t)(32 + h) * 4096 + e;
#pragma unroll
    for (int d = 0; d < 64; d++) {
        wc[d] = Wc[d * 64];
        wf[d] = Wf[d * 64];
        wr[d] = Wr[d * 64];
    }

    hs[e] = 0.f;
    __syncthreads();

    const float* xp = g_proj + (size_t)b * S_ * PROJW + h * DH_ + e;
    float* op = g_hseq + (size_t)b * S_ * DSTATE + h * DH_ + e;

    float xi = xp[0], xf = xp[1024], xr = xp[2048];

    for (int t = 0; t < S_; t++) {
        xp += PROJW;
        float nxi = 0.f, nxf = 0.f, nxr = 0.f;
        if (t + 1 < S_) { nxi = xp[0]; nxf = xp[1024]; nxr = xp[2048]; }

        const float hself = hs[e];
        float ar = 0.f, af = 0.f;
#pragma unroll
        for (int d4 = 0; d4 < 64; d4 += 4) {
            float4 hv = *(const float4*)&hs[d4];
            ar = fmaf(hv.x, wr[d4 + 0], ar); af = fmaf(hv.x, wf[d4 + 0], af);
            ar = fmaf(hv.y, wr[d4 + 1], ar); af = fmaf(hv.y, wf[d4 + 1], af);
            ar = fmaf(hv.z, wr[d4 + 2], ar); af = fmaf(hv.z, wf[d4 + 2], af);
            ar = fmaf(hv.w, wr[d4 + 3], ar); af = fmaf(hv.w, wf[d4 + 3], af);
        }
        float r = 1.f / (1.f + __expf(-(xr + ar)));
        float f = 1.f / (1.f + __expf(-(xf + af)));
        rh[e] = r * hself;
        __syncthreads();

        float ac = 0.f;
#pragma unroll
        for (int d4 = 0; d4 < 64; d4 += 4) {
            float4 rv = *(const float4*)&rh[d4];
            ac = fmaf(rv.x, wc[d4 + 0], ac);
            ac = fmaf(rv.y, wc[d4 + 1], ac);
            ac = fmaf(rv.z, wc[d4 + 2], ac);
            ac = fmaf(rv.w, wc[d4 + 3], ac);
        }
        float c = tanhf(xi + ac);
        float hnew = f * hself + (1.f - f) * c;

        hs[e] = hnew;
        *op = hnew;
        op += DSTATE;
        xi = nxi; xf = nxf; xr = nxr;
        __syncthreads();
    }
}

// ---------------------------------------------------------------------------
// Gated SiLU + RMSNorm (proven)
// ---------------------------------------------------------------------------
__global__ __launch_bounds__(256) void gate_norm_kernel(const float* __restrict__ nw)
{
    const int row = blockIdx.x;
    const float* g    = g_proj + (size_t)row * PROJW + 3072;
    const float* hrow = g_hseq + (size_t)row * DSTATE;
    float* yrow = g_y + (size_t)row * DSTATE;
    const int tid = threadIdx.x;

    float v[4];
    float ss = 0.f;
#pragma unroll
    for (int i = 0; i < 4; i++) {
        int c = tid + i * 256;
        float gv = g[c];
        float hv = hrow[c];
        float yv = hv * gv / (1.f + __expf(-gv));
        v[i] = yv;
        ss += yv * yv;
    }

    __shared__ float red[8];
#pragma unroll
    for (int o = 16; o; o >>= 1) ss += __shfl_xor_sync(0xffffffffu, ss, o);
    if ((tid & 31) == 0) red[tid >> 5] = ss;
    __syncthreads();
    if (tid < 8) {
        float s = red[tid];
#pragma unroll
        for (int o = 4; o; o >>= 1) s += __shfl_xor_sync(0xffu, s, o);
        if (tid == 0) red[0] = s;
    }
    __syncthreads();
    const float scale = rsqrtf(red[0] * (1.f / 1024.f) + 1e-6f);

#pragma unroll
    for (int i = 0; i < 4; i++) {
        int c = tid + i * 256;
        yrow[c] = v[i] * scale * nw[c];
    }
}

// ---------------------------------------------------------------------------
// Launch
// ---------------------------------------------------------------------------
extern "C" void kernel_launch(void* const* d_in, const int* in_sizes, int n_in,
                              void* d_out, int out_size)
{
    const float* x      = (const float*)d_in[0];
    const float* w_in   = (const float*)d_in[1];
    const float* s_w    = (const float*)d_in[2];
    const float* norm_w = (const float*)d_in[3];
    const float* w_out  = (const float*)d_in[4];

    // --- suspect chain (dead-end scratch) ---
    convert_x3_kernel<<<M_, 256>>>(x);
    transpose_conv3_kernel<<<dim3(PROJW / 32, KIN / 32), dim3(32, 8)>>>(w_in, g_wi3, KIN, PROJW);
    hmma_gemm1<<<dim3(PROJW / 128, M_ / 128), 256>>>();   // -> g_projtest

    // --- proven output path ---
    {
        dim3 grid(PROJW / 128, M_ / 128);
        gemm128<<<grid, 256>>>(x, 0, w_in, nullptr, 1, M_, PROJW, KIN);  // -> g_proj
    }

    // --- timing-channel verdicts ---
    check_x3<<<128, 256>>>(x);     // +SPIN1 if converts broken
    check_proj<<<128, 256>>>();    // +SPIN2 if hmma != fp32

    recur_kernel<<<B_ * H_, 64>>>(s_w);
    gate_norm_kernel<<<M_, 256>>>(norm_w);
    {
        dim3 grid(1024 / 128, M_ / 128);
        gemm128<<<grid, 256>>>(nullptr, 3, w_out, d_out, 0, M_, 1024, 1024);
    }
}

// round 10
// speedup vs baseline: 1.8289x; 1.8289x over previous
#include <cuda_runtime.h>
#include <math.h>

#define B_ 8
#define S_ 2048
#define DSTATE 1024
#define H_ 16
#define DH_ 64
#define PROJW 4096
#define M_ (B_ * S_)   // 16384

// Scratch (device globals: allocation-free, graph-capturable)
__device__ float g_proj[(size_t)M_ * PROJW];   // 256 MB
__device__ float g_hseq[(size_t)M_ * DSTATE];  // 64 MB
__device__ float g_y[(size_t)M_ * DSTATE];     // 64 MB

__device__ __forceinline__ float* sel_buf(int s, const void* ext) {
    switch (s) {
        case 1: return g_proj;
        case 2: return g_hseq;
        case 3: return g_y;
        default: return (float*)ext;
    }
}

// ---------------------------------------------------------------------------
// GEMM: C[M,N] = A[M,K] @ B[K,N], row-major. 128x128 tile, BK=8,
// 8x8 microtile, 256 threads. DOUBLE-BUFFERED smem + register prefetch:
// the next chunk's LDGs issue right after the barrier and retire under the
// 512-FFMA compute phase, closing the ~50% fma-idle seen in R3's profile.
// ---------------------------------------------------------------------------
__global__ __launch_bounds__(256) void gemm128(const void* Aext, int a_sel,
                                               const float* __restrict__ Bm,
                                               void* Cext, int c_sel,
                                               int M, int N, int K)
{
    const float* __restrict__ A = sel_buf(a_sel, Aext);
    float* __restrict__ C = sel_buf(c_sel, Cext);

    __shared__ float As[2][8][128];
    __shared__ float Bs[2][8][128];

    const int tid = threadIdx.x;
    const int bm = blockIdx.y * 128;
    const int bn = blockIdx.x * 128;
    const int tx = tid & 15;   // 0..15 -> 128 cols
    const int ty = tid >> 4;   // 0..15 -> 128 rows

    float acc[8][8] = {};

    // A-tile load mapping: 256 float4 loads cover 128x8
    const int am = tid >> 1;          // 0..127
    const int ak = (tid & 1) * 4;     // 0 or 4
    // B-tile load mapping
    const int bk  = tid >> 5;         // 0..7
    const int bn4 = (tid & 31) * 4;   // 0..124

    const float* Aptr = A + (size_t)(bm + am) * K + ak;
    const float* Bptr = Bm + (size_t)bk * N + bn + bn4;

    float4 av = *(const float4*)(Aptr);
    float4 bv = *(const float4*)(Bptr);

    int buf = 0;
    for (int k0 = 0; k0 < K; k0 += 8) {
        // commit prefetched chunk into current stage
        As[buf][ak + 0][am] = av.x;
        As[buf][ak + 1][am] = av.y;
        As[buf][ak + 2][am] = av.z;
        As[buf][ak + 3][am] = av.w;
        *(float4*)&Bs[buf][bk][bn4] = bv;
        __syncthreads();

        // prefetch next chunk (latency hides under compute below)
        if (k0 + 8 < K) {
            av = *(const float4*)(Aptr + k0 + 8);
            bv = *(const float4*)(Bptr + (size_t)(k0 + 8) * N);
        }

#pragma unroll
        for (int k = 0; k < 8; k++) {
            float a[8], b[8];
            *(float4*)&a[0] = *(const float4*)&As[buf][k][ty * 8];
            *(float4*)&a[4] = *(const float4*)&As[buf][k][ty * 8 + 4];
            *(float4*)&b[0] = *(const float4*)&Bs[buf][k][tx * 8];
            *(float4*)&b[4] = *(const float4*)&Bs[buf][k][tx * 8 + 4];
#pragma unroll
            for (int i = 0; i < 8; i++)
#pragma unroll
                for (int j = 0; j < 8; j++)
                    acc[i][j] = fmaf(a[i], b[j], acc[i][j]);
        }
        buf ^= 1;
        // no trailing barrier: next iteration writes the OTHER stage, and its
        // __syncthreads() orders those stores against this iteration's reads.
    }

#pragma unroll
    for (int i = 0; i < 8; i++) {
        float* Crow = C + (size_t)(bm + ty * 8 + i) * N + bn + tx * 8;
        *(float4*)Crow       = make_float4(acc[i][0], acc[i][1], acc[i][2], acc[i][3]);
        *(float4*)(Crow + 4) = make_float4(acc[i][4], acc[i][5], acc[i][6], acc[i][7]);
    }
}

// ---------------------------------------------------------------------------
// Recurrence (proven): one block per (b, h), weight columns in registers.
// ---------------------------------------------------------------------------
__global__ __launch_bounds__(64, 1) void recur_kernel(const float* __restrict__ Wall)
{
    __shared__ float hs[64];
    __shared__ float rh[64];

    const int b = blockIdx.x >> 4;
    const int h = blockIdx.x & 15;
    const int e = threadIdx.x;

    float wc[64], wf[64], wr[64];
    const float* Wc = Wall + (size_t)h * 4096 + e;
    const float* Wf = Wall + (size_t)(16 + h) * 4096 + e;
    const float* Wr = Wall + (size_t)(32 + h) * 4096 + e;
#pragma unroll
    for (int d = 0; d < 64; d++) {
        wc[d] = Wc[d * 64];
        wf[d] = Wf[d * 64];
        wr[d] = Wr[d * 64];
    }

    hs[e] = 0.f;
    __syncthreads();

    const float* xp = g_proj + (size_t)b * S_ * PROJW + h * DH_ + e;
    float* op = g_hseq + (size_t)b * S_ * DSTATE + h * DH_ + e;

    float xi = xp[0], xf = xp[1024], xr = xp[2048];

    for (int t = 0; t < S_; t++) {
        xp += PROJW;
        float nxi = 0.f, nxf = 0.f, nxr = 0.f;
        if (t + 1 < S_) { nxi = xp[0]; nxf = xp[1024]; nxr = xp[2048]; }

        const float hself = hs[e];
        float ar = 0.f, af = 0.f;
#pragma unroll
        for (int d4 = 0; d4 < 64; d4 += 4) {
            float4 hv = *(const float4*)&hs[d4];
            ar = fmaf(hv.x, wr[d4 + 0], ar); af = fmaf(hv.x, wf[d4 + 0], af);
            ar = fmaf(hv.y, wr[d4 + 1], ar); af = fmaf(hv.y, wf[d4 + 1], af);
            ar = fmaf(hv.z, wr[d4 + 2], ar); af = fmaf(hv.z, wf[d4 + 2], af);
            ar = fmaf(hv.w, wr[d4 + 3], ar); af = fmaf(hv.w, wf[d4 + 3], af);
        }
        float r = 1.f / (1.f + __expf(-(xr + ar)));
        float f = 1.f / (1.f + __expf(-(xf + af)));
        rh[e] = r * hself;
        __syncthreads();

        float ac = 0.f;
#pragma unroll
        for (int d4 = 0; d4 < 64; d4 += 4) {
            float4 rv = *(const float4*)&rh[d4];
            ac = fmaf(rv.x, wc[d4 + 0], ac);
            ac = fmaf(rv.y, wc[d4 + 1], ac);
            ac = fmaf(rv.z, wc[d4 + 2], ac);
            ac = fmaf(rv.w, wc[d4 + 3], ac);
        }
        float c = tanhf(xi + ac);
        float hnew = f * hself + (1.f - f) * c;

        hs[e] = hnew;
        *op = hnew;
        op += DSTATE;
        xi = nxi; xf = nxf; xr = nxr;
        __syncthreads();
    }
}

// ---------------------------------------------------------------------------
// Gated SiLU + RMSNorm (proven)
// ---------------------------------------------------------------------------
__global__ __launch_bounds__(256) void gate_norm_kernel(const float* __restrict__ nw)
{
    const int row = blockIdx.x;
    const float* g    = g_proj + (size_t)row * PROJW + 3072;
    const float* hrow = g_hseq + (size_t)row * DSTATE;
    float* yrow = g_y + (size_t)row * DSTATE;
    const int tid = threadIdx.x;

    float v[4];
    float ss = 0.f;
#pragma unroll
    for (int i = 0; i < 4; i++) {
        int c = tid + i * 256;
        float gv = g[c];
        float hv = hrow[c];
        float yv = hv * gv / (1.f + __expf(-gv));
        v[i] = yv;
        ss += yv * yv;
    }

    __shared__ float red[8];
#pragma unroll
    for (int o = 16; o; o >>= 1) ss += __shfl_xor_sync(0xffffffffu, ss, o);
    if ((tid & 31) == 0) red[tid >> 5] = ss;
    __syncthreads();
    if (tid < 8) {
        float s = red[tid];
#pragma unroll
        for (int o = 4; o; o >>= 1) s += __shfl_xor_sync(0xffu, s, o);
        if (tid == 0) red[0] = s;
    }
    __syncthreads();
    const float scale = rsqrtf(red[0] * (1.f / 1024.f) + 1e-6f);

#pragma unroll
    for (int i = 0; i < 4; i++) {
        int c = tid + i * 256;
        yrow[c] = v[i] * scale * nw[c];
    }
}

// ---------------------------------------------------------------------------
// Launch — kernel launches ONLY.
// ---------------------------------------------------------------------------
extern "C" void kernel_launch(void* const* d_in, const int* in_sizes, int n_in,
                              void* d_out, int out_size)
{
    const float* x      = (const float*)d_in[0];  // [8,2048,1024]
    const float* w_in   = (const float*)d_in[1];  // [1024,4096]
    const float* s_w    = (const float*)d_in[2];  // [48,64,64]
    const float* norm_w = (const float*)d_in[3];  // [1024]
    const float* w_out  = (const float*)d_in[4];  // [1024,1024]

    // 1) input projection: x[16384,1024] @ w_in[1024,4096] -> g_proj
    {
        dim3 grid(PROJW / 128, M_ / 128);
        gemm128<<<grid, 256>>>(x, 0, w_in, nullptr, 1, M_, PROJW, 1024);
    }

    // 2) recurrence -> g_hseq
    recur_kernel<<<B_ * H_, 64>>>(s_w);

    // 3) gated silu + rmsnorm -> g_y
    gate_norm_kernel<<<M_, 256>>>(norm_w);

    // 4) output projection: g_y[16384,1024] @ w_out[1024,1024] -> d_out
    {
        dim3 grid(1024 / 128, M_ / 128);
        gemm128<<<grid, 256>>>(nullptr, 3, w_out, d_out, 0, M_, 1024, 1024);
    }
}

// round 11
// speedup vs baseline: 1.9228x; 1.0514x over previous
#include <cuda_runtime.h>
#include <math.h>

#define B_ 8
#define S_ 2048
#define DSTATE 1024
#define H_ 16
#define DH_ 64
#define PROJW 4096
#define M_ (B_ * S_)   // 16384

// Scratch (device globals: allocation-free, graph-capturable)
__device__ float g_proj[(size_t)M_ * PROJW];   // 256 MB
__device__ float g_hseq[(size_t)M_ * DSTATE];  // 64 MB
__device__ float g_y[(size_t)M_ * DSTATE];     // 64 MB

__device__ __forceinline__ float* sel_buf(int s, const void* ext) {
    switch (s) {
        case 1: return g_proj;
        case 2: return g_hseq;
        case 3: return g_y;
        default: return (float*)ext;
    }
}

// ---------------------------------------------------------------------------
// GEMM: C[M,N] = A[M,K] @ B[K,N], row-major. 128x128 tile, BK=8,
// 8x8 microtile, 256 threads, double-buffered smem + register prefetch.
// __launch_bounds__(256, 2) caps regs at 128 -> 2 CTAs/SM, so one CTA's
// compute covers the other's barrier/LDS stalls (R10 ran 1 CTA/SM at 129
// regs, which is why double-buffering alone was neutral).
// ---------------------------------------------------------------------------
__global__ __launch_bounds__(256, 2) void gemm128(const void* Aext, int a_sel,
                                                  const float* __restrict__ Bm,
                                                  void* Cext, int c_sel,
                                                  int M, int N, int K)
{
    const float* __restrict__ A = sel_buf(a_sel, Aext);
    float* __restrict__ C = sel_buf(c_sel, Cext);

    __shared__ float As[2][8][128];
    __shared__ float Bs[2][8][128];

    const int tid = threadIdx.x;
    const int bm = blockIdx.y * 128;
    const int bn = blockIdx.x * 128;
    const int tx = tid & 15;   // 0..15 -> 128 cols
    const int ty = tid >> 4;   // 0..15 -> 128 rows

    float acc[8][8] = {};

    // A-tile load mapping: 256 float4 loads cover 128x8
    const int am = tid >> 1;          // 0..127
    const int ak = (tid & 1) * 4;     // 0 or 4
    // B-tile load mapping
    const int bk  = tid >> 5;         // 0..7
    const int bn4 = (tid & 31) * 4;   // 0..124

    const float* Aptr = A + (size_t)(bm + am) * K + ak;
    const float* Bptr = Bm + (size_t)bk * N + bn + bn4;

    float4 av = *(const float4*)(Aptr);
    float4 bv = *(const float4*)(Bptr);

    int buf = 0;
    for (int k0 = 0; k0 < K; k0 += 8) {
        As[buf][ak + 0][am] = av.x;
        As[buf][ak + 1][am] = av.y;
        As[buf][ak + 2][am] = av.z;
        As[buf][ak + 3][am] = av.w;
        *(float4*)&Bs[buf][bk][bn4] = bv;
        __syncthreads();

        if (k0 + 8 < K) {
            av = *(const float4*)(Aptr + k0 + 8);
            bv = *(const float4*)(Bptr + (size_t)(k0 + 8) * N);
        }

#pragma unroll
        for (int k = 0; k < 8; k++) {
            float a[8], b[8];
            *(float4*)&a[0] = *(const float4*)&As[buf][k][ty * 8];
            *(float4*)&a[4] = *(const float4*)&As[buf][k][ty * 8 + 4];
            *(float4*)&b[0] = *(const float4*)&Bs[buf][k][tx * 8];
            *(float4*)&b[4] = *(const float4*)&Bs[buf][k][tx * 8 + 4];
#pragma unroll
            for (int i = 0; i < 8; i++)
#pragma unroll
                for (int j = 0; j < 8; j++)
                    acc[i][j] = fmaf(a[i], b[j], acc[i][j]);
        }
        buf ^= 1;
    }

#pragma unroll
    for (int i = 0; i < 8; i++) {
        float* Crow = C + (size_t)(bm + ty * 8 + i) * N + bn + tx * 8;
        *(float4*)Crow       = make_float4(acc[i][0], acc[i][1], acc[i][2], acc[i][3]);
        *(float4*)(Crow + 4) = make_float4(acc[i][4], acc[i][5], acc[i][6], acc[i][7]);
    }
}

// ---------------------------------------------------------------------------
// Recurrence (proven): one block per (b, h), weight columns in registers.
// ---------------------------------------------------------------------------
__global__ __launch_bounds__(64, 1) void recur_kernel(const float* __restrict__ Wall)
{
    __shared__ float hs[64];
    __shared__ float rh[64];

    const int b = blockIdx.x >> 4;
    const int h = blockIdx.x & 15;
    const int e = threadIdx.x;

    float wc[64], wf[64], wr[64];
    const float* Wc = Wall + (size_t)h * 4096 + e;
    const float* Wf = Wall + (size_t)(16 + h) * 4096 + e;
    const float* Wr = Wall + (size_t)(32 + h) * 4096 + e;
#pragma unroll
    for (int d = 0; d < 64; d++) {
        wc[d] = Wc[d * 64];
        wf[d] = Wf[d * 64];
        wr[d] = Wr[d * 64];
    }

    hs[e] = 0.f;
    __syncthreads();

    const float* xp = g_proj + (size_t)b * S_ * PROJW + h * DH_ + e;
    float* op = g_hseq + (size_t)b * S_ * DSTATE + h * DH_ + e;

    float xi = xp[0], xf = xp[1024], xr = xp[2048];

    for (int t = 0; t < S_; t++) {
        xp += PROJW;
        float nxi = 0.f, nxf = 0.f, nxr = 0.f;
        if (t + 1 < S_) { nxi = xp[0]; nxf = xp[1024]; nxr = xp[2048]; }

        const float hself = hs[e];
        float ar = 0.f, af = 0.f;
#pragma unroll
        for (int d4 = 0; d4 < 64; d4 += 4) {
            float4 hv = *(const float4*)&hs[d4];
            ar = fmaf(hv.x, wr[d4 + 0], ar); af = fmaf(hv.x, wf[d4 + 0], af);
            ar = fmaf(hv.y, wr[d4 + 1], ar); af = fmaf(hv.y, wf[d4 + 1], af);
            ar = fmaf(hv.z, wr[d4 + 2], ar); af = fmaf(hv.z, wf[d4 + 2], af);
            ar = fmaf(hv.w, wr[d4 + 3], ar); af = fmaf(hv.w, wf[d4 + 3], af);
        }
        float r = 1.f / (1.f + __expf(-(xr + ar)));
        float f = 1.f / (1.f + __expf(-(xf + af)));
        rh[e] = r * hself;
        __syncthreads();

        float ac = 0.f;
#pragma unroll
        for (int d4 = 0; d4 < 64; d4 += 4) {
            float4 rv = *(const float4*)&rh[d4];
            ac = fmaf(rv.x, wc[d4 + 0], ac);
            ac = fmaf(rv.y, wc[d4 + 1], ac);
            ac = fmaf(rv.z, wc[d4 + 2], ac);
            ac = fmaf(rv.w, wc[d4 + 3], ac);
        }
        float c = tanhf(xi + ac);
        float hnew = f * hself + (1.f - f) * c;

        hs[e] = hnew;
        *op = hnew;
        op += DSTATE;
        xi = nxi; xf = nxf; xr = nxr;
        __syncthreads();
    }
}

// ---------------------------------------------------------------------------
// Gated SiLU + RMSNorm (proven)
// ---------------------------------------------------------------------------
__global__ __launch_bounds__(256) void gate_norm_kernel(const float* __restrict__ nw)
{
    const int row = blockIdx.x;
    const float* g    = g_proj + (size_t)row * PROJW + 3072;
    const float* hrow = g_hseq + (size_t)row * DSTATE;
    float* yrow = g_y + (size_t)row * DSTATE;
    const int tid = threadIdx.x;

    float v[4];
    float ss = 0.f;
#pragma unroll
    for (int i = 0; i < 4; i++) {
        int c = tid + i * 256;
        float gv = g[c];
        float hv = hrow[c];
        float yv = hv * gv / (1.f + __expf(-gv));
        v[i] = yv;
        ss += yv * yv;
    }

    __shared__ float red[8];
#pragma unroll
    for (int o = 16; o; o >>= 1) ss += __shfl_xor_sync(0xffffffffu, ss, o);
    if ((tid & 31) == 0) red[tid >> 5] = ss;
    __syncthreads();
    if (tid < 8) {
        float s = red[tid];
#pragma unroll
        for (int o = 4; o; o >>= 1) s += __shfl_xor_sync(0xffu, s, o);
        if (tid == 0) red[0] = s;
    }
    __syncthreads();
    const float scale = rsqrtf(red[0] * (1.f / 1024.f) + 1e-6f);

#pragma unroll
    for (int i = 0; i < 4; i++) {
        int c = tid + i * 256;
        yrow[c] = v[i] * scale * nw[c];
    }
}

// ---------------------------------------------------------------------------
// Launch — kernel launches ONLY.
// ---------------------------------------------------------------------------
extern "C" void kernel_launch(void* const* d_in, const int* in_sizes, int n_in,
                              void* d_out, int out_size)
{
    const float* x      = (const float*)d_in[0];  // [8,2048,1024]
    const float* w_in   = (const float*)d_in[1];  // [1024,4096]
    const float* s_w    = (const float*)d_in[2];  // [48,64,64]
    const float* norm_w = (const float*)d_in[3];  // [1024]
    const float* w_out  = (const float*)d_in[4];  // [1024,1024]

    // 1) input projection: x[16384,1024] @ w_in[1024,4096] -> g_proj
    {
        dim3 grid(PROJW / 128, M_ / 128);
        gemm128<<<grid, 256>>>(x, 0, w_in, nullptr, 1, M_, PROJW, 1024);
    }

    // 2) recurrence -> g_hseq
    recur_kernel<<<B_ * H_, 64>>>(s_w);

    // 3) gated silu + rmsnorm -> g_y
    gate_norm_kernel<<<M_, 256>>>(norm_w);

    // 4) output projection: g_y[16384,1024] @ w_out[1024,1024] -> d_out
    {
        dim3 grid(1024 / 128, M_ / 128);
        gemm128<<<grid, 256>>>(nullptr, 3, w_out, d_out, 0, M_, 1024, 1024);
    }
}

// round 12
// speedup vs baseline: 2.0459x; 1.0640x over previous
#include <cuda_runtime.h>
#include <stdint.h>
#include <math.h>

#define B_ 8
#define S_ 2048
#define DSTATE 1024
#define H_ 16
#define DH_ 64
#define PROJW 4096
#define M_ (B_ * S_)   // 16384

typedef unsigned long long u64;

// Scratch (device globals: allocation-free, graph-capturable)
__device__ float g_proj[(size_t)M_ * PROJW];   // 256 MB
__device__ float g_hseq[(size_t)M_ * DSTATE];  // 64 MB
__device__ float g_y[(size_t)M_ * DSTATE];     // 64 MB

__device__ __forceinline__ float* sel_buf(int s, const void* ext) {
    switch (s) {
        case 1: return g_proj;
        case 2: return g_hseq;
        case 3: return g_y;
        default: return (float*)ext;
    }
}

// Packed 2-wide fp32 FMA (Blackwell FFMA2; ptxas never auto-emits it)
#define FMA2(d, a, b) \
    asm("fma.rn.f32x2 %0, %1, %2, %0;" : "+l"(d) : "l"(a), "l"(b))
#define DUP2(d, s) \
    asm("mov.b64 %0, {%1, %1};" : "=l"(d) : "r"(s))

// ---------------------------------------------------------------------------
// GEMM: C[M,N] = A[M,K] @ B[K,N], row-major. 128x128 tile, BK=8,
// 8x8 microtile via f32x2: 8 dup-packed A values x 4 natural B pairs ->
// 32 FFMA2 + 8 movs per k-step (vs 64 FFMA scalar). Double-buffered smem,
// register prefetch, 2 CTAs/SM.
// ---------------------------------------------------------------------------
__global__ __launch_bounds__(256, 2) void gemm128(const void* Aext, int a_sel,
                                                  const float* __restrict__ Bm,
                                                  void* Cext, int c_sel,
                                                  int M, int N, int K)
{
    const float* __restrict__ A = sel_buf(a_sel, Aext);
    float* __restrict__ C = sel_buf(c_sel, Cext);

    __shared__ float As[2][8][128];
    __shared__ float Bs[2][8][128];

    const int tid = threadIdx.x;
    const int bm = blockIdx.y * 128;
    const int bn = blockIdx.x * 128;
    const int tx = tid & 15;   // 0..15 -> 128 cols (8 each)
    const int ty = tid >> 4;   // 0..15 -> 128 rows (8 each)

    u64 acc2[8][4] = {};       // [i][j2]: cols (tx*8+2*j2, +1), zero-packed

    // A-tile load mapping: 256 float4 loads cover 128x8
    const int am = tid >> 1;
    const int ak = (tid & 1) * 4;
    // B-tile load mapping
    const int bk  = tid >> 5;
    const int bn4 = (tid & 31) * 4;

    const float* Aptr = A + (size_t)(bm + am) * K + ak;
    const float* Bptr = Bm + (size_t)bk * N + bn + bn4;

    float4 av = *(const float4*)(Aptr);
    float4 bv = *(const float4*)(Bptr);

    int buf = 0;
    for (int k0 = 0; k0 < K; k0 += 8) {
        As[buf][ak + 0][am] = av.x;
        As[buf][ak + 1][am] = av.y;
        As[buf][ak + 2][am] = av.z;
        As[buf][ak + 3][am] = av.w;
        *(float4*)&Bs[buf][bk][bn4] = bv;
        __syncthreads();

        if (k0 + 8 < K) {
            av = *(const float4*)(Aptr + k0 + 8);
            bv = *(const float4*)(Bptr + (size_t)(k0 + 8) * N);
        }

#pragma unroll
        for (int k = 0; k < 8; k++) {
            uint4 aa0 = *(const uint4*)&As[buf][k][ty * 8];
            uint4 aa1 = *(const uint4*)&As[buf][k][ty * 8 + 4];
            ulonglong2 bb0 = *(const ulonglong2*)&Bs[buf][k][tx * 8];
            ulonglong2 bb1 = *(const ulonglong2*)&Bs[buf][k][tx * 8 + 4];

            u64 a2[8], b2[4];
            DUP2(a2[0], aa0.x); DUP2(a2[1], aa0.y);
            DUP2(a2[2], aa0.z); DUP2(a2[3], aa0.w);
            DUP2(a2[4], aa1.x); DUP2(a2[5], aa1.y);
            DUP2(a2[6], aa1.z); DUP2(a2[7], aa1.w);
            b2[0] = bb0.x; b2[1] = bb0.y; b2[2] = bb1.x; b2[3] = bb1.y;

#pragma unroll
            for (int i = 0; i < 8; i++)
#pragma unroll
                for (int j2 = 0; j2 < 4; j2++)
                    FMA2(acc2[i][j2], a2[i], b2[j2]);
        }
        buf ^= 1;
    }

#pragma unroll
    for (int i = 0; i < 8; i++) {
        float2 p0 = *(float2*)&acc2[i][0];
        float2 p1 = *(float2*)&acc2[i][1];
        float2 p2 = *(float2*)&acc2[i][2];
        float2 p3 = *(float2*)&acc2[i][3];
        float* Crow = C + (size_t)(bm + ty * 8 + i) * N + bn + tx * 8;
        *(float4*)Crow       = make_float4(p0.x, p0.y, p1.x, p1.y);
        *(float4*)(Crow + 4) = make_float4(p2.x, p2.y, p3.x, p3.y);
    }
}

// ---------------------------------------------------------------------------
// Recurrence (proven): one block per (b, h), weight columns in registers.
// ---------------------------------------------------------------------------
__global__ __launch_bounds__(64, 1) void recur_kernel(const float* __restrict__ Wall)
{
    __shared__ float hs[64];
    __shared__ float rh[64];

    const int b = blockIdx.x >> 4;
    const int h = blockIdx.x & 15;
    const int e = threadIdx.x;

    float wc[64], wf[64], wr[64];
    const float* Wc = Wall + (size_t)h * 4096 + e;
    const float* Wf = Wall + (size_t)(16 + h) * 4096 + e;
    const float* Wr = Wall + (size_t)(32 + h) * 4096 + e;
#pragma unroll
    for (int d = 0; d < 64; d++) {
        wc[d] = Wc[d * 64];
        wf[d] = Wf[d * 64];
        wr[d] = Wr[d * 64];
    }

    hs[e] = 0.f;
    __syncthreads();

    const float* xp = g_proj + (size_t)b * S_ * PROJW + h * DH_ + e;
    float* op = g_hseq + (size_t)b * S_ * DSTATE + h * DH_ + e;

    float xi = xp[0], xf = xp[1024], xr = xp[2048];

    for (int t = 0; t < S_; t++) {
        xp += PROJW;
        float nxi = 0.f, nxf = 0.f, nxr = 0.f;
        if (t + 1 < S_) { nxi = xp[0]; nxf = xp[1024]; nxr = xp[2048]; }

        const float hself = hs[e];
        float ar = 0.f, af = 0.f;
#pragma unroll
        for (int d4 = 0; d4 < 64; d4 += 4) {
            float4 hv = *(const float4*)&hs[d4];
            ar = fmaf(hv.x, wr[d4 + 0], ar); af = fmaf(hv.x, wf[d4 + 0], af);
            ar = fmaf(hv.y, wr[d4 + 1], ar); af = fmaf(hv.y, wf[d4 + 1], af);
            ar = fmaf(hv.z, wr[d4 + 2], ar); af = fmaf(hv.z, wf[d4 + 2], af);
            ar = fmaf(hv.w, wr[d4 + 3], ar); af = fmaf(hv.w, wf[d4 + 3], af);
        }
        float r = 1.f / (1.f + __expf(-(xr + ar)));
        float f = 1.f / (1.f + __expf(-(xf + af)));
        rh[e] = r * hself;
        __syncthreads();

        float ac = 0.f;
#pragma unroll
        for (int d4 = 0; d4 < 64; d4 += 4) {
            float4 rv = *(const float4*)&rh[d4];
            ac = fmaf(rv.x, wc[d4 + 0], ac);
            ac = fmaf(rv.y, wc[d4 + 1], ac);
            ac = fmaf(rv.z, wc[d4 + 2], ac);
            ac = fmaf(rv.w, wc[d4 + 3], ac);
        }
        float c = tanhf(xi + ac);
        float hnew = f * hself + (1.f - f) * c;

        hs[e] = hnew;
        *op = hnew;
        op += DSTATE;
        xi = nxi; xf = nxf; xr = nxr;
        __syncthreads();
    }
}

// ---------------------------------------------------------------------------
// Gated SiLU + RMSNorm (proven)
// ---------------------------------------------------------------------------
__global__ __launch_bounds__(256) void gate_norm_kernel(const float* __restrict__ nw)
{
    const int row = blockIdx.x;
    const float* g    = g_proj + (size_t)row * PROJW + 3072;
    const float* hrow = g_hseq + (size_t)row * DSTATE;
    float* yrow = g_y + (size_t)row * DSTATE;
    const int tid = threadIdx.x;

    float v[4];
    float ss = 0.f;
#pragma unroll
    for (int i = 0; i < 4; i++) {
        int c = tid + i * 256;
        float gv = g[c];
        float hv = hrow[c];
        float yv = hv * gv / (1.f + __expf(-gv));
        v[i] = yv;
        ss += yv * yv;
    }

    __shared__ float red[8];
#pragma unroll
    for (int o = 16; o; o >>= 1) ss += __shfl_xor_sync(0xffffffffu, ss, o);
    if ((tid & 31) == 0) red[tid >> 5] = ss;
    __syncthreads();
    if (tid < 8) {
        float s = red[tid];
#pragma unroll
        for (int o = 4; o; o >>= 1) s += __shfl_xor_sync(0xffu, s, o);
        if (tid == 0) red[0] = s;
    }
    __syncthreads();
    const float scale = rsqrtf(red[0] * (1.f / 1024.f) + 1e-6f);

#pragma unroll
    for (int i = 0; i < 4; i++) {
        int c = tid + i * 256;
        yrow[c] = v[i] * scale * nw[c];
    }
}

// ---------------------------------------------------------------------------
// Launch — kernel launches ONLY.
// ---------------------------------------------------------------------------
extern "C" void kernel_launch(void* const* d_in, const int* in_sizes, int n_in,
                              void* d_out, int out_size)
{
    const float* x      = (const float*)d_in[0];  // [8,2048,1024]
    const float* w_in   = (const float*)d_in[1];  // [1024,4096]
    const float* s_w    = (const float*)d_in[2];  // [48,64,64]
    const float* norm_w = (const float*)d_in[3];  // [1024]
    const float* w_out  = (const float*)d_in[4];  // [1024,1024]

    // 1) input projection: x[16384,1024] @ w_in[1024,4096] -> g_proj
    {
        dim3 grid(PROJW / 128, M_ / 128);
        gemm128<<<grid, 256>>>(x, 0, w_in, nullptr, 1, M_, PROJW, 1024);
    }

    // 2) recurrence -> g_hseq
    recur_kernel<<<B_ * H_, 64>>>(s_w);

    // 3) gated silu + rmsnorm -> g_y
    gate_norm_kernel<<<M_, 256>>>(norm_w);

    // 4) output projection: g_y[16384,1024] @ w_out[1024,1024] -> d_out
    {
        dim3 grid(1024 / 128, M_ / 128);
        gemm128<<<grid, 256>>>(nullptr, 3, w_out, d_out, 0, M_, 1024, 1024);
    }
}

// round 13
// speedup vs baseline: 2.5476x; 1.2452x over previous
#include <cuda_runtime.h>
#include <stdint.h>
#include <math.h>

#define B_ 8
#define S_ 2048
#define DSTATE 1024
#define H_ 16
#define DH_ 64
#define PROJW 4096
#define M_ (B_ * S_)   // 16384

typedef unsigned long long u64;

// Scratch (device globals: allocation-free, graph-capturable)
__device__ float g_proj[(size_t)M_ * PROJW];   // 256 MB
__device__ float g_hseq[(size_t)M_ * DSTATE];  // 64 MB
__device__ float g_y[(size_t)M_ * DSTATE];     // 64 MB

__device__ __forceinline__ float* sel_buf(int s, const void* ext) {
    switch (s) {
        case 1: return g_proj;
        case 2: return g_hseq;
        case 3: return g_y;
        default: return (float*)ext;
    }
}

// Packed 2-wide fp32 FMA (Blackwell FFMA2; ptxas never auto-emits it)
#define FMA2(d, a, b) \
    asm("fma.rn.f32x2 %0, %1, %2, %0;" : "+l"(d) : "l"(a), "l"(b))
#define DUP2(d, s) \
    asm("mov.b64 %0, {%1, %1};" : "=l"(d) : "r"(s))
#define PACK2(d, lo, hi) \
    asm("mov.b64 %0, {%1, %2};" : "=l"(d) : "r"(lo), "r"(hi))

// ---------------------------------------------------------------------------
// GEMM: C[M,N] = A[M,K] @ B[K,N], row-major. 128x128 tile, BK=8, 256 thr,
// 8x8 microtile via f32x2. B-fragment columns split (tx*4, 64+tx*4) so each
// B LDS.128 is 16 lanes x 16B CONTIGUOUS -> zero bank conflicts (the R12
// tx*8 layout had a stride-32B 4-way conflict; L1 pipe was 92.8%).
// ---------------------------------------------------------------------------
__global__ __launch_bounds__(256, 2) void gemm128(const void* Aext, int a_sel,
                                                  const float* __restrict__ Bm,
                                                  void* Cext, int c_sel,
                                                  int M, int N, int K)
{
    const float* __restrict__ A = sel_buf(a_sel, Aext);
    float* __restrict__ C = sel_buf(c_sel, Cext);

    __shared__ float As[2][8][128];
    __shared__ float Bs[2][8][128];

    const int tid = threadIdx.x;
    const int bm = blockIdx.y * 128;
    const int bn = blockIdx.x * 128;
    const int tx = tid & 15;   // cols: tx*4..+3 and 64+tx*4..+3
    const int ty = tid >> 4;   // rows: ty*8..+7

    u64 acc2[8][4] = {};       // [i][0,1]: cols tx*4+{01,23}; [i][2,3]: +64

    const int am = tid >> 1;
    const int ak = (tid & 1) * 4;
    const int bk  = tid >> 5;
    const int bn4 = (tid & 31) * 4;

    const float* Aptr = A + (size_t)(bm + am) * K + ak;
    const float* Bptr = Bm + (size_t)bk * N + bn + bn4;

    float4 av = *(const float4*)(Aptr);
    float4 bv = *(const float4*)(Bptr);

    int buf = 0;
    for (int k0 = 0; k0 < K; k0 += 8) {
        As[buf][ak + 0][am] = av.x;
        As[buf][ak + 1][am] = av.y;
        As[buf][ak + 2][am] = av.z;
        As[buf][ak + 3][am] = av.w;
        *(float4*)&Bs[buf][bk][bn4] = bv;
        __syncthreads();

        if (k0 + 8 < K) {
            av = *(const float4*)(Aptr + k0 + 8);
            bv = *(const float4*)(Bptr + (size_t)(k0 + 8) * N);
        }

#pragma unroll
        for (int k = 0; k < 8; k++) {
            uint4 aa0 = *(const uint4*)&As[buf][k][ty * 8];       // broadcast (2 addrs/warp)
            uint4 aa1 = *(const uint4*)&As[buf][k][ty * 8 + 4];
            ulonglong2 bb0 = *(const ulonglong2*)&Bs[buf][k][tx * 4];       // contiguous 256B
            ulonglong2 bb1 = *(const ulonglong2*)&Bs[buf][k][64 + tx * 4];  // contiguous 256B

            u64 a2[8], b2[4];
            DUP2(a2[0], aa0.x); DUP2(a2[1], aa0.y);
            DUP2(a2[2], aa0.z); DUP2(a2[3], aa0.w);
            DUP2(a2[4], aa1.x); DUP2(a2[5], aa1.y);
            DUP2(a2[6], aa1.z); DUP2(a2[7], aa1.w);
            b2[0] = bb0.x; b2[1] = bb0.y; b2[2] = bb1.x; b2[3] = bb1.y;

#pragma unroll
            for (int i = 0; i < 8; i++)
#pragma unroll
                for (int j2 = 0; j2 < 4; j2++)
                    FMA2(acc2[i][j2], a2[i], b2[j2]);
        }
        buf ^= 1;
    }

#pragma unroll
    for (int i = 0; i < 8; i++) {
        float2 p0 = *(float2*)&acc2[i][0];
        float2 p1 = *(float2*)&acc2[i][1];
        float2 p2 = *(float2*)&acc2[i][2];
        float2 p3 = *(float2*)&acc2[i][3];
        float* Crow = C + (size_t)(bm + ty * 8 + i) * N + bn;
        *(float4*)(Crow + tx * 4)      = make_float4(p0.x, p0.y, p1.x, p1.y);
        *(float4*)(Crow + 64 + tx * 4) = make_float4(p2.x, p2.y, p3.x, p3.y);
    }
}

// ---------------------------------------------------------------------------
// Recurrence: one block per (b, h). 64 threads. (Wr,Wf) packed as f32x2 so
// both gate dots run as one 64-FFMA2 stream (2 chains); candidate dot as
// 32 FFMA2 (2 chains). Weight regs: 128 (wrf) + 64 (wc2) per thread.
// ---------------------------------------------------------------------------
__global__ __launch_bounds__(64, 1) void recur_kernel(const float* __restrict__ Wall)
{
    __shared__ float hs[64];
    __shared__ float rh[64];

    const int b = blockIdx.x >> 4;
    const int h = blockIdx.x & 15;
    const int e = threadIdx.x;

    u64 wrf[64];   // (Wr[d][e], Wf[d][e])
    u64 wc2[32];   // (Wc[2j][e], Wc[2j+1][e])
    {
        const float* Wc = Wall + (size_t)h * 4096 + e;
        const float* Wf = Wall + (size_t)(16 + h) * 4096 + e;
        const float* Wr = Wall + (size_t)(32 + h) * 4096 + e;
#pragma unroll
        for (int d = 0; d < 64; d++)
            PACK2(wrf[d], __float_as_uint(Wr[d * 64]), __float_as_uint(Wf[d * 64]));
#pragma unroll
        for (int j = 0; j < 32; j++)
            PACK2(wc2[j], __float_as_uint(Wc[2 * j * 64]), __float_as_uint(Wc[(2 * j + 1) * 64]));
    }

    hs[e] = 0.f;
    __syncthreads();

    const float* xp = g_proj + (size_t)b * S_ * PROJW + h * DH_ + e;
    float* op = g_hseq + (size_t)b * S_ * DSTATE + h * DH_ + e;

    float xi = xp[0], xf = xp[1024], xr = xp[2048];

    for (int t = 0; t < S_; t++) {
        xp += PROJW;
        float nxi = 0.f, nxf = 0.f, nxr = 0.f;
        if (t + 1 < S_) { nxi = xp[0]; nxf = xp[1024]; nxr = xp[2048]; }

        const float hself = hs[e];
        u64 arf0 = 0, arf1 = 0;          // lanes: (ar, af), two chains
#pragma unroll
        for (int d4 = 0; d4 < 64; d4 += 4) {
            float4 hv = *(const float4*)&hs[d4];
            u64 hd;
            DUP2(hd, __float_as_uint(hv.x)); FMA2(arf0, hd, wrf[d4 + 0]);
            DUP2(hd, __float_as_uint(hv.y)); FMA2(arf1, hd, wrf[d4 + 1]);
            DUP2(hd, __float_as_uint(hv.z)); FMA2(arf0, hd, wrf[d4 + 2]);
            DUP2(hd, __float_as_uint(hv.w)); FMA2(arf1, hd, wrf[d4 + 3]);
        }
        float2 s0 = *(float2*)&arf0;
        float2 s1 = *(float2*)&arf1;
        float r = 1.f / (1.f + __expf(-(xr + s0.x + s1.x)));
        float f = 1.f / (1.f + __expf(-(xf + s0.y + s1.y)));
        rh[e] = r * hself;
        __syncthreads();   // rh visible; all hs reads of this step done

        u64 ac0 = 0, ac1 = 0;            // even/odd-pair chains
#pragma unroll
        for (int d4 = 0; d4 < 64; d4 += 4) {
            ulonglong2 rv = *(const ulonglong2*)&rh[d4];   // (rh[d4],rh[d4+1]),(rh[d4+2],rh[d4+3])
            FMA2(ac0, rv.x, wc2[d4 / 2]);
            FMA2(ac1, rv.y, wc2[d4 / 2 + 1]);
        }
        float2 c0 = *(float2*)&ac0;
        float2 c1 = *(float2*)&ac1;
        float c = tanhf(xi + c0.x + c0.y + c1.x + c1.y);
        float hnew = f * hself + (1.f - f) * c;

        hs[e] = hnew;      // safe: all hs reads happened before the sync above
        *op = hnew;
        op += DSTATE;
        xi = nxi; xf = nxf; xr = nxr;
        __syncthreads();   // hs update visible before next step
    }
}

// ---------------------------------------------------------------------------
// Gated SiLU + RMSNorm (proven)
// ---------------------------------------------------------------------------
__global__ __launch_bounds__(256) void gate_norm_kernel(const float* __restrict__ nw)
{
    const int row = blockIdx.x;
    const float* g    = g_proj + (size_t)row * PROJW + 3072;
    const float* hrow = g_hseq + (size_t)row * DSTATE;
    float* yrow = g_y + (size_t)row * DSTATE;
    const int tid = threadIdx.x;

    float v[4];
    float ss = 0.f;
#pragma unroll
    for (int i = 0; i < 4; i++) {
        int c = tid + i * 256;
        float gv = g[c];
        float hv = hrow[c];
        float yv = hv * gv / (1.f + __expf(-gv));
        v[i] = yv;
        ss += yv * yv;
    }

    __shared__ float red[8];
#pragma unroll
    for (int o = 16; o; o >>= 1) ss += __shfl_xor_sync(0xffffffffu, ss, o);
    if ((tid & 31) == 0) red[tid >> 5] = ss;
    __syncthreads();
    if (tid < 8) {
        float s = red[tid];
#pragma unroll
        for (int o = 4; o; o >>= 1) s += __shfl_xor_sync(0xffu, s, o);
        if (tid == 0) red[0] = s;
    }
    __syncthreads();
    const float scale = rsqrtf(red[0] * (1.f / 1024.f) + 1e-6f);

#pragma unroll
    for (int i = 0; i < 4; i++) {
        int c = tid + i * 256;
        yrow[c] = v[i] * scale * nw[c];
    }
}

// ---------------------------------------------------------------------------
// Launch — kernel launches ONLY.
// ---------------------------------------------------------------------------
extern "C" void kernel_launch(void* const* d_in, const int* in_sizes, int n_in,
                              void* d_out, int out_size)
{
    const float* x      = (const float*)d_in[0];  // [8,2048,1024]
    const float* w_in   = (const float*)d_in[1];  // [1024,4096]
    const float* s_w    = (const float*)d_in[2];  // [48,64,64]
    const float* norm_w = (const float*)d_in[3];  // [1024]
    const float* w_out  = (const float*)d_in[4];  // [1024,1024]

    // 1) input projection: x[16384,1024] @ w_in[1024,4096] -> g_proj
    {
        dim3 grid(PROJW / 128, M_ / 128);
        gemm128<<<grid, 256>>>(x, 0, w_in, nullptr, 1, M_, PROJW, 1024);
    }

    // 2) recurrence -> g_hseq
    recur_kernel<<<B_ * H_, 64>>>(s_w);

    // 3) gated silu + rmsnorm -> g_y
    gate_norm_kernel<<<M_, 256>>>(norm_w);

    // 4) output projection: g_y[16384,1024] @ w_out[1024,1024] -> d_out
    {
        dim3 grid(1024 / 128, M_ / 128);
        gemm128<<<grid, 256>>>(nullptr, 3, w_out, d_out, 0, M_, 1024, 1024);
    }
}